// round 2
// baseline (speedup 1.0000x reference)
#include <cuda_runtime.h>
#include <math.h>

#define BQ 16
#define SEQ 1024
#define RDIM 1024
#define NHID 1024
#define HEADS 8
#define DKH 128

// ---------------- scratch (static device allocations; no cudaMalloc allowed) ----
__device__ float g_q[(size_t)BQ * SEQ * NHID];      // 64 MB
__device__ float g_k[(size_t)BQ * SEQ * NHID];      // 64 MB
__device__ float g_v[(size_t)BQ * SEQ * NHID];      // 64 MB
__device__ float g_atted[(size_t)BQ * SEQ * NHID];  // 64 MB
__device__ float g_att[(size_t)BQ * HEADS * SEQ * SEQ]; // 512 MB (fallback if att not in d_out)
__device__ unsigned char g_mask[(size_t)BQ * SEQ];  // canonical mask (1 = masked)
__device__ int g_mask_mode;                          // 0=u8, 1=i32, 2=f32

// =================================================================================
// Mask dtype detection: scan first 4096 32-bit words (safe for u8/i32/f32 layouts).
//   - word == 0x3F800000 seen, and nothing outside {0, 0x3F800000}  -> f32
//   - all words in {0,1}                                            -> i32
//   - anything else (packed bool bytes)                             -> u8
// =================================================================================
__global__ void detect_mask_mode(const unsigned int* __restrict__ m)
{
    __shared__ int s_non01f;  // word outside {0,1,0x3F800000}
    __shared__ int s_f32w;    // word == 0x3F800000
    __shared__ int s_gt1;     // word > 1 (but could be f32 one)
    if (threadIdx.x == 0) { s_non01f = 0; s_f32w = 0; s_gt1 = 0; }
    __syncthreads();
    int ln = 0, lf = 0, lg = 0;
    for (int i = threadIdx.x; i < 4096; i += blockDim.x) {
        unsigned int w = m[i];
        if (w == 0x3F800000u) lf = 1;
        else if (w > 1u) { ln = 1; }
        if (w > 1u) lg = 1;
    }
    if (ln) atomicOr(&s_non01f, 1);
    if (lf) atomicOr(&s_f32w, 1);
    if (lg) atomicOr(&s_gt1, 1);
    __syncthreads();
    if (threadIdx.x == 0) {
        int mode;
        if (s_non01f) mode = 0;            // u8 packed bools
        else if (s_f32w) mode = 2;         // f32
        else mode = 1;                     // i32 (all 0/1)
        g_mask_mode = mode;
    }
}

__global__ void convert_mask(const void* __restrict__ m, unsigned char* __restrict__ outm, int n)
{
    int i = blockIdx.x * blockDim.x + threadIdx.x;
    if (i >= n) return;
    int mode = g_mask_mode;
    unsigned char r;
    if (mode == 0)      r = ((const unsigned char*)m)[i] ? 1 : 0;
    else if (mode == 1) r = ((const int*)m)[i] ? 1 : 0;
    else                r = (((const float*)m)[i] != 0.0f) ? 1 : 0;
    outm[i] = r;
}

// =================================================================================
// Generic NN GEMM:  C[z] = A[z] @ B[z] + bias, 64x64 block tile, 4x4 per thread.
// =================================================================================
__global__ __launch_bounds__(256) void gemm_nn(
    const float* __restrict__ A, int lda, long long sA,
    const float* __restrict__ Bm, int ldb, long long sB1, long long sB2,
    const float* __restrict__ bias,
    float* __restrict__ C, int ldc, long long sC1, long long sC2,
    int M, int N, int Kc)
{
    int z = blockIdx.z;
    const float* Ab = A + (long long)z * sA;
    const float* Bb = Bm + (long long)(z / HEADS) * sB1 + (long long)(z % HEADS) * sB2;
    float* Cb = C + (long long)(z / HEADS) * sC1 + (long long)(z % HEADS) * sC2;

    __shared__ float As[16][68];  // As[k][m]
    __shared__ float Bs[16][68];  // Bs[k][n]

    int tid = threadIdx.x;
    int tx = tid & 15, ty = tid >> 4;
    int m0 = blockIdx.y * 64, n0 = blockIdx.x * 64;

    int amRow = tid >> 2;          // 0..63
    int akCol = (tid & 3) * 4;     // 0,4,8,12
    int bkRow = tid >> 4;          // 0..15
    int bnCol = (tid & 15) * 4;    // 0..60

    float acc[4][4];
#pragma unroll
    for (int i = 0; i < 4; i++)
#pragma unroll
        for (int j = 0; j < 4; j++) acc[i][j] = 0.f;

    for (int kt = 0; kt < Kc; kt += 16) {
        float4 av = *(const float4*)(Ab + (long long)(m0 + amRow) * lda + kt + akCol);
        float4 bv = *(const float4*)(Bb + (long long)(kt + bkRow) * ldb + n0 + bnCol);
        __syncthreads();
        As[akCol + 0][amRow] = av.x;
        As[akCol + 1][amRow] = av.y;
        As[akCol + 2][amRow] = av.z;
        As[akCol + 3][amRow] = av.w;
        *(float4*)&Bs[bkRow][bnCol] = bv;
        __syncthreads();
#pragma unroll
        for (int kk = 0; kk < 16; kk++) {
            float a[4], b[4];
#pragma unroll
            for (int i = 0; i < 4; i++) a[i] = As[kk][ty * 4 + i];
#pragma unroll
            for (int j = 0; j < 4; j++) b[j] = Bs[kk][tx * 4 + j];
#pragma unroll
            for (int i = 0; i < 4; i++)
#pragma unroll
                for (int j = 0; j < 4; j++) acc[i][j] = fmaf(a[i], b[j], acc[i][j]);
        }
    }

    float bb[4];
#pragma unroll
    for (int j = 0; j < 4; j++) bb[j] = bias ? bias[n0 + tx * 4 + j] : 0.f;
#pragma unroll
    for (int i = 0; i < 4; i++) {
        long long crow = (long long)(m0 + ty * 4 + i) * ldc + n0 + tx * 4;
#pragma unroll
        for (int j = 0; j < 4; j++) Cb[crow + j] = acc[i][j] + bb[j];
    }
}

// =================================================================================
// Scores (NT GEMM) fused with scale + mask (canonical u8 mask: 1 = masked -> -1e9)
// =================================================================================
__global__ __launch_bounds__(256) void scores_nt(
    const float* __restrict__ Q, const float* __restrict__ Km,
    const unsigned char* __restrict__ mask,
    float* __restrict__ att, float scale)
{
    int z = blockIdx.z;
    int b = z >> 3, h = z & 7;
    const float* Ab = Q + (long long)b * SEQ * NHID + h * DKH;
    const float* Bb = Km + (long long)b * SEQ * NHID + h * DKH;
    float* Cb = att + (long long)z * SEQ * SEQ;
    const unsigned char* mb = mask + (long long)b * SEQ;

    __shared__ float As[16][68];
    __shared__ float Bs[16][68];

    int tid = threadIdx.x;
    int tx = tid & 15, ty = tid >> 4;
    int m0 = blockIdx.y * 64, n0 = blockIdx.x * 64;

    int row = tid >> 2;
    int dq = (tid & 3) * 4;

    float acc[4][4];
#pragma unroll
    for (int i = 0; i < 4; i++)
#pragma unroll
        for (int j = 0; j < 4; j++) acc[i][j] = 0.f;

    for (int kt = 0; kt < DKH; kt += 16) {
        float4 av = *(const float4*)(Ab + (long long)(m0 + row) * NHID + kt + dq);
        float4 bv = *(const float4*)(Bb + (long long)(n0 + row) * NHID + kt + dq);
        __syncthreads();
        As[dq + 0][row] = av.x;
        As[dq + 1][row] = av.y;
        As[dq + 2][row] = av.z;
        As[dq + 3][row] = av.w;
        Bs[dq + 0][row] = bv.x;
        Bs[dq + 1][row] = bv.y;
        Bs[dq + 2][row] = bv.z;
        Bs[dq + 3][row] = bv.w;
        __syncthreads();
#pragma unroll
        for (int kk = 0; kk < 16; kk++) {
            float a[4], b2[4];
#pragma unroll
            for (int i = 0; i < 4; i++) a[i] = As[kk][ty * 4 + i];
#pragma unroll
            for (int j = 0; j < 4; j++) b2[j] = Bs[kk][tx * 4 + j];
#pragma unroll
            for (int i = 0; i < 4; i++)
#pragma unroll
                for (int j = 0; j < 4; j++) acc[i][j] = fmaf(a[i], b2[j], acc[i][j]);
        }
    }

#pragma unroll
    for (int i = 0; i < 4; i++) {
        long long crow = (long long)(m0 + ty * 4 + i) * SEQ + n0 + tx * 4;
#pragma unroll
        for (int j = 0; j < 4; j++) {
            int col = n0 + tx * 4 + j;
            Cb[crow + j] = mb[col] ? -1e9f : acc[i][j] * scale;
        }
    }
}

// =================================================================================
// Row softmax over last dim (SEQ=1024), one block (128 thr) per row, in place.
// =================================================================================
__global__ __launch_bounds__(128) void softmax_rows(float* __restrict__ att)
{
    long long rowi = blockIdx.x;
    float* p = att + rowi * SEQ;
    int t = threadIdx.x;
    int w = t >> 5, l = t & 31;
    __shared__ float smx[4], ssm[4];

    float v[8];
    float mx = -INFINITY;
#pragma unroll
    for (int i = 0; i < 8; i++) {
        v[i] = p[t + i * 128];
        mx = fmaxf(mx, v[i]);
    }
#pragma unroll
    for (int o = 16; o; o >>= 1) mx = fmaxf(mx, __shfl_xor_sync(0xffffffffu, mx, o));
    if (l == 0) smx[w] = mx;
    __syncthreads();
    mx = fmaxf(fmaxf(smx[0], smx[1]), fmaxf(smx[2], smx[3]));

    float s = 0.f;
#pragma unroll
    for (int i = 0; i < 8; i++) {
        v[i] = expf(v[i] - mx);
        s += v[i];
    }
#pragma unroll
    for (int o = 16; o; o >>= 1) s += __shfl_xor_sync(0xffffffffu, s, o);
    if (l == 0) ssm[w] = s;
    __syncthreads();
    s = ssm[0] + ssm[1] + ssm[2] + ssm[3];
    float inv = 1.f / s;
#pragma unroll
    for (int i = 0; i < 8; i++) p[t + i * 128] = v[i] * inv;
}

// =================================================================================
extern "C" void kernel_launch(void* const* d_in, const int* in_sizes, int n_in,
                              void* d_out, int out_size)
{
    const float* v_in  = (const float*)d_in[0];
    const float* key   = (const float*)d_in[1];
    const float* query = (const float*)d_in[2];
    const void*  mask  = d_in[3];
    const float* Wq = (const float*)d_in[4];
    const float* bq = (const float*)d_in[5];
    const float* Wk = (const float*)d_in[6];
    const float* bk = (const float*)d_in[7];
    const float* Wv = (const float*)d_in[8];
    const float* bv = (const float*)d_in[9];
    const float* Wm = (const float*)d_in[10];
    const float* bm = (const float*)d_in[11];
    float* out = (float*)d_out;

    const long long ATTED_N = (long long)BQ * SEQ * NHID;          // 16777216
    const long long ATT_N   = (long long)BQ * HEADS * SEQ * SEQ;   // 134217728

    float* g_q_p; float* g_k_p; float* g_v_p; float* g_atted_p; float* g_att_p;
    unsigned char* g_mask_p;
    cudaGetSymbolAddress((void**)&g_q_p, g_q);
    cudaGetSymbolAddress((void**)&g_k_p, g_k);
    cudaGetSymbolAddress((void**)&g_v_p, g_v);
    cudaGetSymbolAddress((void**)&g_atted_p, g_atted);
    cudaGetSymbolAddress((void**)&g_att_p, g_att);
    cudaGetSymbolAddress((void**)&g_mask_p, g_mask);

    // decide output layout
    float* att_ptr;
    float* atted_ptr;
    bool write_atted = true;
    if ((long long)out_size >= ATTED_N + ATT_N) {
        atted_ptr = out;
        att_ptr = out + ATTED_N;
    } else if ((long long)out_size == ATT_N) {
        att_ptr = out;
        atted_ptr = g_atted_p;
        write_atted = false;
    } else {
        atted_ptr = out;
        att_ptr = g_att_p;
    }

    const int M = BQ * SEQ;          // 16384
    dim3 blk(256);

    // Canonicalize mask (dtype-agnostic)
    detect_mask_mode<<<1, 256>>>((const unsigned int*)mask);
    convert_mask<<<(BQ * SEQ + 255) / 256, 256>>>(mask, g_mask_p, BQ * SEQ);

    // Projections: q/k/v = X @ W + b
    {
        dim3 grid(NHID / 64, M / 64, 1);
        gemm_nn<<<grid, blk>>>(query, RDIM, 0, Wq, NHID, 0, 0, bq,
                               g_q_p, NHID, 0, 0, M, NHID, RDIM);
        gemm_nn<<<grid, blk>>>(key,   RDIM, 0, Wk, NHID, 0, 0, bk,
                               g_k_p, NHID, 0, 0, M, NHID, RDIM);
        gemm_nn<<<grid, blk>>>(v_in,  RDIM, 0, Wv, NHID, 0, 0, bv,
                               g_v_p, NHID, 0, 0, M, NHID, RDIM);
    }

    // Scores + mask + scale
    {
        dim3 grid(SEQ / 64, SEQ / 64, BQ * HEADS);
        float scale = 1.0f / sqrtf((float)DKH);
        scores_nt<<<grid, blk>>>(g_q_p, g_k_p, g_mask_p, att_ptr, scale);
    }

    // Softmax in place
    {
        dim3 grid((unsigned)(BQ * HEADS * SEQ));
        softmax_rows<<<grid, dim3(128)>>>(att_ptr);
    }

    // PV: atted[b,h] = att[b,h] @ V[b,h]
    {
        dim3 grid(DKH / 64, SEQ / 64, BQ * HEADS);
        gemm_nn<<<grid, blk>>>(att_ptr, SEQ, (long long)SEQ * SEQ,
                               g_v_p, NHID, (long long)SEQ * NHID, DKH,
                               nullptr,
                               g_atted_p, NHID, (long long)SEQ * NHID, DKH,
                               SEQ, DKH, SEQ);
    }

    // Output projection: out = atted @ Wm + bm
    if (write_atted) {
        dim3 grid(NHID / 64, M / 64, 1);
        gemm_nn<<<grid, blk>>>(g_atted_p, NHID, 0, Wm, NHID, 0, 0, bm,
                               atted_ptr, NHID, 0, 0, M, NHID, NHID);
    }
}

// round 4
// speedup vs baseline: 2.8365x; 2.8365x over previous
#include <cuda_runtime.h>
#include <cuda_bf16.h>
#include <math.h>
#include <stdint.h>

#define BQ 16
#define SEQ 1024
#define RDIM 1024
#define NHID 1024
#define HEADS 8
#define DKH 128

// ======================= static scratch ==========================================
__device__ __nv_bfloat16 g_inqh[(size_t)BQ * SEQ * RDIM], g_inql[(size_t)BQ * SEQ * RDIM];
__device__ __nv_bfloat16 g_inkh[(size_t)BQ * SEQ * RDIM], g_inkl[(size_t)BQ * SEQ * RDIM];
__device__ __nv_bfloat16 g_invh[(size_t)BQ * SEQ * RDIM], g_invl[(size_t)BQ * SEQ * RDIM];
__device__ __nv_bfloat16 g_wqh[(size_t)NHID * RDIM], g_wql[(size_t)NHID * RDIM];
__device__ __nv_bfloat16 g_wkh[(size_t)NHID * RDIM], g_wkl[(size_t)NHID * RDIM];
__device__ __nv_bfloat16 g_wvh[(size_t)NHID * RDIM], g_wvl[(size_t)NHID * RDIM];
__device__ __nv_bfloat16 g_wmh[(size_t)NHID * NHID], g_wml[(size_t)NHID * NHID];
__device__ __nv_bfloat16 g_qh[(size_t)BQ * SEQ * NHID], g_ql[(size_t)BQ * SEQ * NHID];
__device__ __nv_bfloat16 g_kh[(size_t)BQ * SEQ * NHID], g_kl[(size_t)BQ * SEQ * NHID];
__device__ __nv_bfloat16 g_vh[(size_t)BQ * SEQ * NHID], g_vl[(size_t)BQ * SEQ * NHID];
__device__ __nv_bfloat16 g_vth[(size_t)BQ * SEQ * NHID], g_vtl[(size_t)BQ * SEQ * NHID];
__device__ __nv_bfloat16 g_atth[(size_t)BQ * HEADS * SEQ * SEQ], g_attl[(size_t)BQ * HEADS * SEQ * SEQ];
__device__ __nv_bfloat16 g_aedh[(size_t)BQ * SEQ * NHID], g_aedl[(size_t)BQ * SEQ * NHID];
__device__ float g_attf[(size_t)BQ * HEADS * SEQ * SEQ]; // fallback if att not in d_out
__device__ unsigned char g_mask[(size_t)BQ * SEQ];
__device__ int g_mask_mode;

// ======================= small helpers ===========================================
__device__ __forceinline__ uint32_t s2u(const void* p) {
    uint32_t a;
    asm("{ .reg .u64 t; cvta.to.shared.u64 t, %1; cvt.u32.u64 %0, t; }" : "=r"(a) : "l"(p));
    return a;
}
__device__ __forceinline__ void f2hl(float x, __nv_bfloat16& h, __nv_bfloat16& l) {
    h = __float2bfloat16(x);
    l = __float2bfloat16(x - __bfloat162float(h));
}
__device__ __forceinline__ void cpa16(uint32_t s, const void* g) {
    asm volatile("cp.async.cg.shared.global [%0], [%1], 16;" :: "r"(s), "l"(g) : "memory");
}
__device__ __forceinline__ void ldm_x4(uint32_t r[4], uint32_t addr) {
    asm volatile("ldmatrix.sync.aligned.m8n8.x4.shared.b16 {%0,%1,%2,%3}, [%4];"
                 : "=r"(r[0]), "=r"(r[1]), "=r"(r[2]), "=r"(r[3]) : "r"(addr));
}
__device__ __forceinline__ void mma_bf16(float* c, const uint32_t* a, uint32_t b0, uint32_t b1) {
    asm volatile(
        "mma.sync.aligned.m16n8k16.row.col.f32.bf16.bf16.f32 "
        "{%0,%1,%2,%3}, {%4,%5,%6,%7}, {%8,%9}, {%0,%1,%2,%3};"
        : "+f"(c[0]), "+f"(c[1]), "+f"(c[2]), "+f"(c[3])
        : "r"(a[0]), "r"(a[1]), "r"(a[2]), "r"(a[3]), "r"(b0), "r"(b1));
}

#define STAGE_BYTES 65536
#define SMEM_TOTAL (2 * STAGE_BYTES)

// ======================= mask canonicalization ===================================
__global__ void detect_mask_mode(const unsigned int* __restrict__ m) {
    __shared__ int s_non01f, s_f32w;
    if (threadIdx.x == 0) { s_non01f = 0; s_f32w = 0; }
    __syncthreads();
    int ln = 0, lf = 0;
    for (int i = threadIdx.x; i < 4096; i += blockDim.x) {
        unsigned int w = m[i];
        if (w == 0x3F800000u) lf = 1;
        else if (w > 1u) ln = 1;
    }
    if (ln) atomicOr(&s_non01f, 1);
    if (lf) atomicOr(&s_f32w, 1);
    __syncthreads();
    if (threadIdx.x == 0) {
        if (s_non01f) g_mask_mode = 0;
        else if (s_f32w) g_mask_mode = 2;
        else g_mask_mode = 1;
    }
}
__global__ void convert_mask(const void* __restrict__ m, unsigned char* __restrict__ outm, int n) {
    int i = blockIdx.x * blockDim.x + threadIdx.x;
    if (i >= n) return;
    int mode = g_mask_mode;
    unsigned char r;
    if (mode == 0)      r = ((const unsigned char*)m)[i] ? 1 : 0;
    else if (mode == 1) r = ((const int*)m)[i] ? 1 : 0;
    else                r = (((const float*)m)[i] != 0.0f) ? 1 : 0;
    outm[i] = r;
}

// ======================= conversions =============================================
__global__ void conv_hl(const float* __restrict__ s, __nv_bfloat16* __restrict__ h,
                        __nv_bfloat16* __restrict__ l, int n4) {
    int i = blockIdx.x * blockDim.x + threadIdx.x;
    if (i >= n4) return;
    float4 v = ((const float4*)s)[i];
    __nv_bfloat16 h0, l0, h1, l1, h2, l2, h3, l3;
    f2hl(v.x, h0, l0); f2hl(v.y, h1, l1); f2hl(v.z, h2, l2); f2hl(v.w, h3, l3);
    __nv_bfloat162 a, b, c, d;
    a.x = h0; a.y = h1; b.x = h2; b.y = h3;
    c.x = l0; c.y = l1; d.x = l2; d.y = l3;
    ((__nv_bfloat162*)h)[i * 2] = a;
    ((__nv_bfloat162*)h)[i * 2 + 1] = b;
    ((__nv_bfloat162*)l)[i * 2] = c;
    ((__nv_bfloat162*)l)[i * 2 + 1] = d;
}

// W [K,N] f32 -> Wt [N,K] hi/lo bf16   (K=N=1024)
__global__ void transW(const float* __restrict__ W, __nv_bfloat16* __restrict__ th,
                       __nv_bfloat16* __restrict__ tl) {
    __shared__ float tile[32][33];
    int n = blockIdx.x * 32 + threadIdx.x;
    int k0 = blockIdx.y * 32;
    for (int i = threadIdx.y; i < 32; i += 8)
        tile[i][threadIdx.x] = W[(long long)(k0 + i) * NHID + n];
    __syncthreads();
    int k = k0 + threadIdx.x;
    int nr0 = blockIdx.x * 32;
    for (int i = threadIdx.y; i < 32; i += 8) {
        float f = tile[threadIdx.x][i];
        __nv_bfloat16 h, l;
        f2hl(f, h, l);
        th[(long long)(nr0 + i) * RDIM + k] = h;
        tl[(long long)(nr0 + i) * RDIM + k] = l;
    }
}

// v [b, t, c] bf16 -> vT [b, c, t]  (per-b 1024x1024 transpose, hi and lo)
__global__ void transV(const __nv_bfloat16* __restrict__ vh, const __nv_bfloat16* __restrict__ vl,
                       __nv_bfloat16* __restrict__ oh, __nv_bfloat16* __restrict__ ol) {
    int b = blockIdx.z;
    __shared__ __nv_bfloat16 th[32][33], tl2[32][33];
    long long base = (long long)b * SEQ * NHID;
    int c = blockIdx.x * 32 + threadIdx.x;
    int t0 = blockIdx.y * 32;
    for (int i = threadIdx.y; i < 32; i += 8) {
        th[i][threadIdx.x] = vh[base + (long long)(t0 + i) * NHID + c];
        tl2[i][threadIdx.x] = vl[base + (long long)(t0 + i) * NHID + c];
    }
    __syncthreads();
    int t = t0 + threadIdx.x;
    int c0 = blockIdx.x * 32;
    for (int i = threadIdx.y; i < 32; i += 8) {
        oh[base + (long long)(c0 + i) * SEQ + t] = th[threadIdx.x][i];
        ol[base + (long long)(c0 + i) * SEQ + t] = tl2[threadIdx.x][i];
    }
}

// ======================= HMMA bf16x3 GEMM ========================================
// C[M,N] = sum_k A[M,K] * Bt[N,K]   (split hi/lo, fp32 accumulate)
// Tile: CTA 128x128, warp 32x64, K-chunk 64, double-buffered cp.async.
// Stage layout: Ah @ +0, Al @ +16K, Bh @ +32K, Bl @ +48K (each 128 rows x 128B, SW128)
__device__ __forceinline__ void load_mat(uint32_t sBase, const __nv_bfloat16* g, int ld, int kt, int tid) {
#pragma unroll
    for (int i = 0; i < 4; i++) {
        int u = tid + (i << 8);
        int r = u >> 3, cu = u & 7;
        uint32_t off = (uint32_t)(r * 128 + cu * 16);
        off ^= (off >> 3) & 0x70;
        cpa16(sBase + off, g + (long long)r * ld + kt + (cu << 3));
    }
}

// swizzled smem address of (row, byteCol) within a 128x128B tile
__device__ __forceinline__ uint32_t swadr(uint32_t base, int row, int bcol) {
    return base + (uint32_t)(row * 128) + (uint32_t)(bcol ^ ((row & 7) << 4));
}

template <int EPI>
__global__ void __launch_bounds__(256) gemm3(
    const __nv_bfloat16* __restrict__ Ah, const __nv_bfloat16* __restrict__ Al,
    int lda, long long sA1, long long sA2,
    const __nv_bfloat16* __restrict__ Bh, const __nv_bfloat16* __restrict__ Bl,
    int ldb, long long sB1, long long sB2,
    const float* __restrict__ bias,
    float* __restrict__ Cf, __nv_bfloat16* __restrict__ Ch, __nv_bfloat16* __restrict__ Cl,
    int ldc, long long sC1, long long sC2,
    int Ktot, const unsigned char* __restrict__ mask, float scale)
{
    extern __shared__ char smem[];
    uint32_t sb = s2u(smem);
    int tid = threadIdx.x;
    int wid = tid >> 5, lane = tid & 31;
    int wm = wid & 3, wn = wid >> 2;     // warp tile: rows wm*32.., cols wn*64..

    int z = blockIdx.z;
    int zb = z / HEADS, zh = z % HEADS;
    int m0 = blockIdx.y * 128, n0 = blockIdx.x * 128;
    const __nv_bfloat16* Azh = Ah + zb * sA1 + zh * sA2 + (long long)m0 * lda;
    const __nv_bfloat16* Azl = Al + zb * sA1 + zh * sA2 + (long long)m0 * lda;
    const __nv_bfloat16* Bzh = Bh + zb * sB1 + zh * sB2 + (long long)n0 * ldb;
    const __nv_bfloat16* Bzl = Bl + zb * sB1 + zh * sB2 + (long long)n0 * ldb;

    float acc[2][8][4];
#pragma unroll
    for (int i = 0; i < 2; i++)
#pragma unroll
        for (int j = 0; j < 8; j++)
#pragma unroll
            for (int q = 0; q < 4; q++) acc[i][j][q] = 0.f;

    int nch = Ktot >> 6;

    // prologue: chunk 0 -> stage 0
    load_mat(sb,         Azh, lda, 0, tid);
    load_mat(sb + 16384, Azl, lda, 0, tid);
    load_mat(sb + 32768, Bzh, ldb, 0, tid);
    load_mat(sb + 49152, Bzl, ldb, 0, tid);
    asm volatile("cp.async.commit_group;" ::: "memory");

    // per-lane ldmatrix address components
    int aRow = (lane & 15);              // + mi*16 + wm*32
    int aColB = (lane >> 4) << 4;        // 0 or 16 bytes, + ks*32
    int bRow = (lane & 7) + ((lane >> 4) << 3);  // + j*16 + wn*64
    int bColB = ((lane >> 3) & 1) << 4;  // 0 or 16 bytes, + ks*32

    for (int c = 0; c < nch; c++) {
        if (c + 1 < nch) {
            uint32_t bq = sb + ((c + 1) & 1) * STAGE_BYTES;
            int kt = (c + 1) << 6;
            load_mat(bq,         Azh, lda, kt, tid);
            load_mat(bq + 16384, Azl, lda, kt, tid);
            load_mat(bq + 32768, Bzh, ldb, kt, tid);
            load_mat(bq + 49152, Bzl, ldb, kt, tid);
            asm volatile("cp.async.commit_group;" ::: "memory");
            asm volatile("cp.async.wait_group 1;" ::: "memory");
        } else {
            asm volatile("cp.async.wait_group 0;" ::: "memory");
        }
        __syncthreads();

        uint32_t bp = sb + (c & 1) * STAGE_BYTES;
        uint32_t aBh = bp, aBl = bp + 16384, bBh = bp + 32768, bBl = bp + 49152;

#pragma unroll
        for (int ks = 0; ks < 4; ks++) {
            int kb = ks << 5;  // 32 bytes per k16 step
            uint32_t ah[2][4], al[2][4];
#pragma unroll
            for (int mi = 0; mi < 2; mi++) {
                int r = wm * 32 + mi * 16 + aRow;
                ldm_x4(ah[mi], swadr(aBh, r, kb + aColB));
                ldm_x4(al[mi], swadr(aBl, r, kb + aColB));
            }
#pragma unroll
            for (int j = 0; j < 4; j++) {
                uint32_t bh4[4], bl4[4];
                int rn = wn * 64 + j * 16 + bRow;
                ldm_x4(bh4, swadr(bBh, rn, kb + bColB));
                ldm_x4(bl4, swadr(bBl, rn, kb + bColB));
                // product-major: hh, hl, lh — spreads same-acc reuse apart
#pragma unroll
                for (int mi = 0; mi < 2; mi++)
#pragma unroll
                    for (int nn = 0; nn < 2; nn++)
                        mma_bf16(acc[mi][2 * j + nn], ah[mi], bh4[nn * 2], bh4[nn * 2 + 1]);
#pragma unroll
                for (int mi = 0; mi < 2; mi++)
#pragma unroll
                    for (int nn = 0; nn < 2; nn++)
                        mma_bf16(acc[mi][2 * j + nn], ah[mi], bl4[nn * 2], bl4[nn * 2 + 1]);
#pragma unroll
                for (int mi = 0; mi < 2; mi++)
#pragma unroll
                    for (int nn = 0; nn < 2; nn++)
                        mma_bf16(acc[mi][2 * j + nn], al[mi], bh4[nn * 2], bh4[nn * 2 + 1]);
            }
        }
        __syncthreads();
    }

    // ---------------- epilogue -----------------
    int gm = m0 + wm * 32;
    int gn = n0 + wn * 64;
    long long cbase = zb * sC1 + zh * sC2;

#pragma unroll
    for (int mi = 0; mi < 2; mi++) {
#pragma unroll
        for (int half = 0; half < 2; half++) {
            int r = gm + mi * 16 + half * 8 + (lane >> 2);
#pragma unroll
            for (int ni = 0; ni < 8; ni++) {
                int cc = gn + ni * 8 + (lane & 3) * 2;
                float f0 = acc[mi][ni][half * 2 + 0];
                float f1 = acc[mi][ni][half * 2 + 1];
                if (EPI == 0) {
                    if (bias) { f0 += bias[cc]; f1 += bias[cc + 1]; }
                    __nv_bfloat16 h0, l0, h1, l1;
                    f2hl(f0, h0, l0); f2hl(f1, h1, l1);
                    __nv_bfloat162 vh2, vl2;
                    vh2.x = h0; vh2.y = h1; vl2.x = l0; vl2.y = l1;
                    *(__nv_bfloat162*)(Ch + cbase + (long long)r * ldc + cc) = vh2;
                    *(__nv_bfloat162*)(Cl + cbase + (long long)r * ldc + cc) = vl2;
                } else if (EPI == 1) {
                    float2 v;
                    v.x = f0 + bias[cc];
                    v.y = f1 + bias[cc + 1];
                    *(float2*)(Cf + cbase + (long long)r * ldc + cc) = v;
                } else {
                    const unsigned char* mb = mask + (long long)zb * SEQ;
                    float2 v;
                    v.x = mb[cc]     ? -1e9f : f0 * scale;
                    v.y = mb[cc + 1] ? -1e9f : f1 * scale;
                    *(float2*)(Cf + cbase + (long long)r * ldc + cc) = v;
                }
            }
        }
    }
}

// ======================= softmax (+ hi/lo bf16 epilogue) =========================
__global__ __launch_bounds__(128) void softmax_rows(float* __restrict__ att,
                                                    __nv_bfloat16* __restrict__ ah,
                                                    __nv_bfloat16* __restrict__ al)
{
    long long rowi = blockIdx.x;
    float* p = att + rowi * SEQ;
    __nv_bfloat16* ph = ah + rowi * SEQ;
    __nv_bfloat16* pl = al + rowi * SEQ;
    int t = threadIdx.x;
    int w = t >> 5, l = t & 31;
    __shared__ float smx[4], ssm[4];

    float v[8];
    float mx = -INFINITY;
#pragma unroll
    for (int i = 0; i < 8; i++) {
        v[i] = p[t + i * 128];
        mx = fmaxf(mx, v[i]);
    }
#pragma unroll
    for (int o = 16; o; o >>= 1) mx = fmaxf(mx, __shfl_xor_sync(0xffffffffu, mx, o));
    if (l == 0) smx[w] = mx;
    __syncthreads();
    mx = fmaxf(fmaxf(smx[0], smx[1]), fmaxf(smx[2], smx[3]));

    float s = 0.f;
#pragma unroll
    for (int i = 0; i < 8; i++) {
        v[i] = expf(v[i] - mx);
        s += v[i];
    }
#pragma unroll
    for (int o = 16; o; o >>= 1) s += __shfl_xor_sync(0xffffffffu, s, o);
    if (l == 0) ssm[w] = s;
    __syncthreads();
    s = ssm[0] + ssm[1] + ssm[2] + ssm[3];
    float inv = 1.f / s;
#pragma unroll
    for (int i = 0; i < 8; i++) {
        float r = v[i] * inv;
        p[t + i * 128] = r;
        __nv_bfloat16 h, lo;
        f2hl(r, h, lo);
        ph[t + i * 128] = h;
        pl[t + i * 128] = lo;
    }
}

// ======================= host ====================================================
extern "C" void kernel_launch(void* const* d_in, const int* in_sizes, int n_in,
                              void* d_out, int out_size)
{
    const float* v_in  = (const float*)d_in[0];
    const float* key   = (const float*)d_in[1];
    const float* query = (const float*)d_in[2];
    const void*  mask  = d_in[3];
    const float* Wq = (const float*)d_in[4];
    const float* bq = (const float*)d_in[5];
    const float* Wk = (const float*)d_in[6];
    const float* bk = (const float*)d_in[7];
    const float* Wv = (const float*)d_in[8];
    const float* bv = (const float*)d_in[9];
    const float* Wm = (const float*)d_in[10];
    const float* bm = (const float*)d_in[11];
    float* out = (float*)d_out;

    const long long ATTED_N = (long long)BQ * SEQ * NHID;
    const long long ATT_N   = (long long)BQ * HEADS * SEQ * SEQ;

#define GETP(sym, ty, var) ty* var; cudaGetSymbolAddress((void**)&var, sym)
    GETP(g_inqh, __nv_bfloat16, inqh); GETP(g_inql, __nv_bfloat16, inql);
    GETP(g_inkh, __nv_bfloat16, inkh); GETP(g_inkl, __nv_bfloat16, inkl);
    GETP(g_invh, __nv_bfloat16, invh); GETP(g_invl, __nv_bfloat16, invl);
    GETP(g_wqh, __nv_bfloat16, wqh); GETP(g_wql, __nv_bfloat16, wql);
    GETP(g_wkh, __nv_bfloat16, wkh); GETP(g_wkl, __nv_bfloat16, wkl);
    GETP(g_wvh, __nv_bfloat16, wvh); GETP(g_wvl, __nv_bfloat16, wvl);
    GETP(g_wmh, __nv_bfloat16, wmh); GETP(g_wml, __nv_bfloat16, wml);
    GETP(g_qh, __nv_bfloat16, qh); GETP(g_ql, __nv_bfloat16, ql);
    GETP(g_kh, __nv_bfloat16, kh); GETP(g_kl, __nv_bfloat16, kl);
    GETP(g_vh, __nv_bfloat16, vh); GETP(g_vl, __nv_bfloat16, vl);
    GETP(g_vth, __nv_bfloat16, vth); GETP(g_vtl, __nv_bfloat16, vtl);
    GETP(g_atth, __nv_bfloat16, atth); GETP(g_attl, __nv_bfloat16, attl);
    GETP(g_aedh, __nv_bfloat16, aedh); GETP(g_aedl, __nv_bfloat16, aedl);
    GETP(g_attf, float, attf);
    GETP(g_mask, unsigned char, maskp);
#undef GETP

    float* att_ptr;
    float* atted_ptr = out;
    if ((long long)out_size >= ATTED_N + ATT_N) {
        att_ptr = out + ATTED_N;
    } else {
        att_ptr = attf;
    }

    cudaFuncSetAttribute(gemm3<0>, cudaFuncAttributeMaxDynamicSharedMemorySize, SMEM_TOTAL);
    cudaFuncSetAttribute(gemm3<1>, cudaFuncAttributeMaxDynamicSharedMemorySize, SMEM_TOTAL);
    cudaFuncSetAttribute(gemm3<2>, cudaFuncAttributeMaxDynamicSharedMemorySize, SMEM_TOTAL);

    // mask
    detect_mask_mode<<<1, 256>>>((const unsigned int*)mask);
    convert_mask<<<(BQ * SEQ + 255) / 256, 256>>>(mask, maskp, BQ * SEQ);

    // input conversions
    {
        int n4 = (int)(ATTED_N / 4);
        int gb = (n4 + 255) / 256;
        conv_hl<<<gb, 256>>>(query, inqh, inql, n4);
        conv_hl<<<gb, 256>>>(key,   inkh, inkl, n4);
        conv_hl<<<gb, 256>>>(v_in,  invh, invl, n4);
    }
    // weight transposes
    {
        dim3 g(32, 32), b(32, 8);
        transW<<<g, b>>>(Wq, wqh, wql);
        transW<<<g, b>>>(Wk, wkh, wkl);
        transW<<<g, b>>>(Wv, wvh, wvl);
        transW<<<g, b>>>(Wm, wmh, wml);
    }

    const float scale = 1.0f / sqrtf((float)DKH);
    dim3 blk(256);

    // Projections: M=16384, N=1024, K=1024 -> hi/lo outputs
    {
        dim3 grid(NHID / 128, (BQ * SEQ) / 128, 1);
        gemm3<0><<<grid, blk, SMEM_TOTAL>>>(inqh, inql, RDIM, 0, 0,
                                            wqh, wql, RDIM, 0, 0, bq,
                                            nullptr, qh, ql, NHID, 0, 0,
                                            RDIM, nullptr, 0.f);
        gemm3<0><<<grid, blk, SMEM_TOTAL>>>(inkh, inkl, RDIM, 0, 0,
                                            wkh, wkl, RDIM, 0, 0, bk,
                                            nullptr, kh, kl, NHID, 0, 0,
                                            RDIM, nullptr, 0.f);
        gemm3<0><<<grid, blk, SMEM_TOTAL>>>(invh, invl, RDIM, 0, 0,
                                            wvh, wvl, RDIM, 0, 0, bv,
                                            nullptr, vh, vl, NHID, 0, 0,
                                            RDIM, nullptr, 0.f);
    }

    // V transpose per batch
    {
        dim3 g(32, 32, BQ), b(32, 8);
        transV<<<g, b>>>(vh, vl, vth, vtl);
    }

    // Scores: per (b,h): M=N=1024, K=128 -> f32 att with scale+mask
    {
        dim3 grid(SEQ / 128, SEQ / 128, BQ * HEADS);
        gemm3<2><<<grid, blk, SMEM_TOTAL>>>(qh, ql, NHID, (long long)SEQ * NHID, DKH,
                                            kh, kl, NHID, (long long)SEQ * NHID, DKH,
                                            nullptr,
                                            att_ptr, nullptr, nullptr, SEQ,
                                            (long long)HEADS * SEQ * SEQ, (long long)SEQ * SEQ,
                                            DKH, maskp, scale);
    }

    // Softmax (+ hi/lo)
    softmax_rows<<<(unsigned)(BQ * HEADS * SEQ), dim3(128)>>>(att_ptr, atth, attl);

    // PV: per (b,h): M=1024, N=128, K=1024 -> hi/lo atted (interleaved [t, NH])
    {
        dim3 grid(1, SEQ / 128, BQ * HEADS);
        gemm3<0><<<grid, blk, SMEM_TOTAL>>>(atth, attl, SEQ,
                                            (long long)HEADS * SEQ * SEQ, (long long)SEQ * SEQ,
                                            vth, vtl, SEQ,
                                            (long long)SEQ * NHID, (long long)DKH * SEQ,
                                            nullptr,
                                            nullptr, aedh, aedl, NHID,
                                            (long long)SEQ * NHID, DKH,
                                            SEQ, nullptr, 0.f);
    }

    // Output projection: M=16384, N=1024, K=1024 -> f32 out
    {
        dim3 grid(NHID / 128, (BQ * SEQ) / 128, 1);
        gemm3<1><<<grid, blk, SMEM_TOTAL>>>(aedh, aedl, NHID, 0, 0,
                                            wmh, wml, NHID, 0, 0, bm,
                                            atted_ptr, nullptr, nullptr, NHID, 0, 0,
                                            NHID, nullptr, 0.f);
    }
}